// round 4
// baseline (speedup 1.0000x reference)
#include <cuda_runtime.h>
#include <cuda_bf16.h>
#include <cstdint>

// Problem constants (fixed by the reference)
constexpr int NN   = 50000;
constexpr int EE   = 800000;
constexpr int DIN  = 128;
constexpr int DHID = 256;

// ---------------- scratch (device globals: allocation-free) ----------------
__device__ __align__(16) float g_deg [NN];
__device__ __align__(16) float g_dinv[NN];
__device__ __align__(16) float g_norm[EE];
__device__ __align__(16) float g_h1  [(size_t)NN * DHID];   // x @ W1^T
__device__ __align__(16) float g_out1[(size_t)NN * DHID];   // aggregated + b1 (pre-relu)
__device__ __align__(16) float g_h2  [(size_t)NN * DIN];    // relu(out1) @ W2^T

// ---------------- small kernels ----------------
__global__ void deg_init_kernel(float* deg, int n) {
    int i = blockIdx.x * blockDim.x + threadIdx.x;
    if (i < n) deg[i] = 1.0f;   // self-loop weight
}

__global__ void deg_acc_kernel(const int* __restrict__ dst,
                               const float* __restrict__ w,
                               float* deg, int e) {
    int i = blockIdx.x * blockDim.x + threadIdx.x;
    if (i < e) atomicAdd(&deg[dst[i]], w[i]);
}

__global__ void dinv_kernel(const float* __restrict__ deg, float* dinv, int n) {
    int i = blockIdx.x * blockDim.x + threadIdx.x;
    if (i < n) dinv[i] = rsqrtf(deg[i]);
}

__global__ void norm_kernel(const int* __restrict__ src,
                            const int* __restrict__ dst,
                            const float* __restrict__ w,
                            const float* __restrict__ dinv,
                            float* norm, int e) {
    int i = blockIdx.x * blockDim.x + threadIdx.x;
    if (i < e) norm[i] = dinv[src[i]] * w[i] * dinv[dst[i]];
}

// out[i, :] = dinv[i]^2 * h[i, :] + bias[:]   (self-loop contribution + bias)
template<int D>
__global__ void self_init_kernel(const float* __restrict__ h,
                                 const float* __restrict__ dinv,
                                 const float* __restrict__ bias,
                                 float* __restrict__ out, int n) {
    int idx = blockIdx.x * blockDim.x + threadIdx.x;
    int total4 = n * (D / 4);
    if (idx >= total4) return;
    int elem = idx * 4;
    int i = elem / D;
    int j = elem % D;
    float s = dinv[i];
    s = s * s;
    float4 hv = *reinterpret_cast<const float4*>(h + (size_t)elem);
    float4 bv = *reinterpret_cast<const float4*>(bias + j);
    float4 o;
    o.x = hv.x * s + bv.x;
    o.y = hv.y * s + bv.y;
    o.z = hv.z * s + bv.z;
    o.w = hv.w * s + bv.w;
    *reinterpret_cast<float4*>(out + (size_t)elem) = o;
}

// One warp per edge: out[dst] += norm * h[src], vectorized red.global.add.v4.f32
template<int D>
__global__ void edge_scatter_kernel(const float* __restrict__ h,
                                    const int* __restrict__ src,
                                    const int* __restrict__ dst,
                                    const float* __restrict__ norm,
                                    float* __restrict__ out, int e) {
    int warp = (blockIdx.x * blockDim.x + threadIdx.x) >> 5;
    int lane = threadIdx.x & 31;
    if (warp >= e) return;
    int s = src[warp];
    int d = dst[warp];
    float nw = norm[warp];
    const float4* hp = reinterpret_cast<const float4*>(h + (size_t)s * D);
    float* op = out + (size_t)d * D;
    #pragma unroll
    for (int it = 0; it < D / 128; it++) {
        float4 v = hp[it * 32 + lane];
        float rx = v.x * nw, ry = v.y * nw, rz = v.z * nw, rw = v.w * nw;
        float* addr = op + (size_t)(it * 32 + lane) * 4;
        asm volatile("red.global.add.v4.f32 [%0], {%1, %2, %3, %4};"
                     :: "l"(addr), "f"(rx), "f"(ry), "f"(rz), "f"(rw)
                     : "memory");
    }
}

// ---------------- tiled SGEMM: C[M,Ncols] = op(A)[M,K] @ B[Ncols,K]^T ----------------
// A row-major [M,K], B row-major [Ncols,K] (both K-contiguous, NT gemm).
// BM=BN=128, BK=8, 256 threads, 8x8 microtile. RELU applies max(0,.) to A loads.
template<bool RELU>
__global__ __launch_bounds__(256)
void sgemm_nt_kernel(const float* __restrict__ A, const float* __restrict__ B,
                     float* __restrict__ C, int M, int Ncols, int K) {
    constexpr int BM = 128, BN = 128, BK = 8, TM = 8, TN = 8;
    __shared__ float As[BK][BM];
    __shared__ float Bs[BK][BN];

    int tid = threadIdx.x;
    int tx = tid % 16;           // 16 cols of threads
    int ty = tid / 16;           // 16 rows of threads
    int block_row = blockIdx.y * BM;
    int block_col = blockIdx.x * BN;

    int ld_row  = tid >> 1;          // 0..127
    int ld_col4 = (tid & 1) * 4;     // 0 or 4

    float acc[TM][TN];
    #pragma unroll
    for (int i = 0; i < TM; i++)
        #pragma unroll
        for (int j = 0; j < TN; j++) acc[i][j] = 0.0f;

    for (int k0 = 0; k0 < K; k0 += BK) {
        // load A tile (guard M)
        float4 av = make_float4(0.f, 0.f, 0.f, 0.f);
        int gr = block_row + ld_row;
        if (gr < M) {
            av = *reinterpret_cast<const float4*>(A + (size_t)gr * K + k0 + ld_col4);
            if (RELU) {
                av.x = fmaxf(av.x, 0.f); av.y = fmaxf(av.y, 0.f);
                av.z = fmaxf(av.z, 0.f); av.w = fmaxf(av.w, 0.f);
            }
        }
        As[ld_col4 + 0][ld_row] = av.x;
        As[ld_col4 + 1][ld_row] = av.y;
        As[ld_col4 + 2][ld_row] = av.z;
        As[ld_col4 + 3][ld_row] = av.w;

        // load B tile (Ncols is a multiple of 128 here: no guard)
        int gn = block_col + ld_row;
        float4 bv = *reinterpret_cast<const float4*>(B + (size_t)gn * K + k0 + ld_col4);
        Bs[ld_col4 + 0][ld_row] = bv.x;
        Bs[ld_col4 + 1][ld_row] = bv.y;
        Bs[ld_col4 + 2][ld_row] = bv.z;
        Bs[ld_col4 + 3][ld_row] = bv.w;

        __syncthreads();

        #pragma unroll
        for (int kk = 0; kk < BK; kk++) {
            float ar[TM], br[TN];
            #pragma unroll
            for (int i = 0; i < TM; i++) ar[i] = As[kk][ty * TM + i];
            #pragma unroll
            for (int j = 0; j < TN; j++) br[j] = Bs[kk][tx * TN + j];
            #pragma unroll
            for (int i = 0; i < TM; i++)
                #pragma unroll
                for (int j = 0; j < TN; j++)
                    acc[i][j] += ar[i] * br[j];
        }
        __syncthreads();
    }

    // store (guard M)
    #pragma unroll
    for (int i = 0; i < TM; i++) {
        int gr = block_row + ty * TM + i;
        if (gr < M) {
            float4 c0 = make_float4(acc[i][0], acc[i][1], acc[i][2], acc[i][3]);
            float4 c1 = make_float4(acc[i][4], acc[i][5], acc[i][6], acc[i][7]);
            float* cp = C + (size_t)gr * Ncols + block_col + tx * TN;
            *reinterpret_cast<float4*>(cp)     = c0;
            *reinterpret_cast<float4*>(cp + 4) = c1;
        }
    }
}

// ---------------- LayerNorm over last dim (D=128), warp per row, in place ----------------
__global__ void layernorm128_kernel(float* __restrict__ io,
                                    const float* __restrict__ gamma,
                                    const float* __restrict__ beta, int n) {
    int row  = blockIdx.x * (blockDim.x >> 5) + (threadIdx.x >> 5);
    int lane = threadIdx.x & 31;
    if (row >= n) return;
    float4 v = reinterpret_cast<const float4*>(io + (size_t)row * 128)[lane];
    float s = v.x + v.y + v.z + v.w;
    #pragma unroll
    for (int o = 16; o; o >>= 1) s += __shfl_xor_sync(0xFFFFFFFFu, s, o);
    float mu = s * (1.0f / 128.0f);
    float dx = v.x - mu, dy = v.y - mu, dz = v.z - mu, dw = v.w - mu;
    float sq = dx * dx + dy * dy + dz * dz + dw * dw;
    #pragma unroll
    for (int o = 16; o; o >>= 1) sq += __shfl_xor_sync(0xFFFFFFFFu, sq, o);
    float inv = rsqrtf(sq * (1.0f / 128.0f) + 1e-5f);
    float4 g = reinterpret_cast<const float4*>(gamma)[lane];
    float4 b = reinterpret_cast<const float4*>(beta)[lane];
    float4 o4;
    o4.x = dx * inv * g.x + b.x;
    o4.y = dy * inv * g.y + b.y;
    o4.z = dz * inv * g.z + b.z;
    o4.w = dw * inv * g.w + b.w;
    reinterpret_cast<float4*>(io + (size_t)row * 128)[lane] = o4;
}

// ---------------- host launcher ----------------
extern "C" void kernel_launch(void* const* d_in, const int* in_sizes, int n_in,
                              void* d_out, int out_size) {
    const float* x     = (const float*)d_in[0];
    const int*   ei    = (const int*)d_in[1];   // JAX x64 disabled: int32
    const float* w     = (const float*)d_in[2];
    const float* W1    = (const float*)d_in[3];
    const float* b1    = (const float*)d_in[4];
    const float* W2    = (const float*)d_in[5];
    const float* b2    = (const float*)d_in[6];
    const float* gamma = (const float*)d_in[7];
    const float* beta  = (const float*)d_in[8];
    float*       out   = (float*)d_out;

    const int* src = ei;        // edge_index[0]
    const int* dst = ei + EE;   // edge_index[1]

    float *deg, *dinv, *nrm, *h1, *out1, *h2;
    cudaGetSymbolAddress((void**)&deg,  g_deg);
    cudaGetSymbolAddress((void**)&dinv, g_dinv);
    cudaGetSymbolAddress((void**)&nrm,  g_norm);
    cudaGetSymbolAddress((void**)&h1,   g_h1);
    cudaGetSymbolAddress((void**)&out1, g_out1);
    cudaGetSymbolAddress((void**)&h2,   g_h2);

    const int T = 256;

    // 1-4: normalization coefficients
    deg_init_kernel<<<(NN + T - 1) / T, T>>>(deg, NN);
    deg_acc_kernel<<<(EE + T - 1) / T, T>>>(dst, w, deg, EE);
    dinv_kernel<<<(NN + T - 1) / T, T>>>(deg, dinv, NN);
    norm_kernel<<<(EE + T - 1) / T, T>>>(src, dst, w, dinv, nrm, EE);

    // 5: h1 = x @ W1^T  [NN, DHID]
    {
        dim3 grid(DHID / 128, (NN + 127) / 128);
        sgemm_nt_kernel<false><<<grid, 256>>>(x, W1, h1, NN, DHID, DIN);
    }

    // 6: out1 = dinv^2 * h1 + b1 (self loop + bias)
    self_init_kernel<DHID><<<(NN * (DHID / 4) + T - 1) / T, T>>>(h1, dinv, b1, out1, NN);

    // 7: out1[dst] += norm * h1[src]
    {
        long long threads = (long long)EE * 32;
        edge_scatter_kernel<DHID><<<(unsigned)((threads + T - 1) / T), T>>>(h1, src, dst, nrm, out1, EE);
    }

    // 8: h2 = relu(out1) @ W2^T  [NN, DIN]
    {
        dim3 grid(DIN / 128, (NN + 127) / 128);
        sgemm_nt_kernel<true><<<grid, 256>>>(out1, W2, h2, NN, DIN, DHID);
    }

    // 9: d_out = dinv^2 * h2 + b2
    self_init_kernel<DIN><<<(NN * (DIN / 4) + T - 1) / T, T>>>(h2, dinv, b2, out, NN);

    // 10: d_out[dst] += norm * h2[src]
    {
        long long threads = (long long)EE * 32;
        edge_scatter_kernel<DIN><<<(unsigned)((threads + T - 1) / T), T>>>(h2, src, dst, nrm, out, EE);
    }

    // 11: LayerNorm in place
    layernorm128_kernel<<<(NN + 7) / 8, 256>>>(out, gamma, beta, NN);
}

// round 6
// speedup vs baseline: 1.3962x; 1.3962x over previous
#include <cuda_runtime.h>
#include <cuda_bf16.h>
#include <cstdint>

// Problem constants (fixed by the reference)
constexpr int NN   = 50000;
constexpr int EE   = 800000;
constexpr int DIN  = 128;
constexpr int DHID = 256;
constexpr int SCAN_B = 256;
constexpr int NBLK   = (NN + SCAN_B - 1) / SCAN_B;   // 196

// ---------------- scratch (device globals: allocation-free) ----------------
__device__ __align__(16) float g_deg  [NN];
__device__ __align__(16) float g_dinv [NN];
__device__ __align__(16) float g_norm [EE];
__device__ __align__(16) int   g_cnt  [NN];       // histogram of dst
__device__ __align__(16) int   g_cur  [NN];       // fill cursor
__device__ __align__(16) int   g_scan [NN];       // per-block inclusive scan
__device__ __align__(16) int   g_bsum [SCAN_B];   // block sums (NBLK <= 256)
__device__ __align__(16) int   g_rowptr[NN + 1];
__device__ __align__(16) int   g_esrc [EE];       // CSR src, sorted by dst
__device__ __align__(16) float g_enorm[EE];       // CSR norm, sorted by dst
__device__ __align__(16) float g_h1   [(size_t)NN * DHID];   // x @ W1^T
__device__ __align__(16) float g_out1 [(size_t)NN * DHID];   // relu(aggregated + b1)
__device__ __align__(16) float g_h2   [(size_t)NN * DIN];    // out1 @ W2^T

// ---------------- normalization coefficient kernels ----------------
__global__ void deg_init_kernel(float* deg, int* cnt, int* cur, int n) {
    int i = blockIdx.x * blockDim.x + threadIdx.x;
    if (i < n) { deg[i] = 1.0f; cnt[i] = 0; cur[i] = 0; }
}

__global__ void deg_acc_kernel(const int* __restrict__ dst,
                               const float* __restrict__ w,
                               float* deg, int* cnt, int e) {
    int i = blockIdx.x * blockDim.x + threadIdx.x;
    if (i < e) {
        int d = dst[i];
        atomicAdd(&deg[d], w[i]);
        atomicAdd(&cnt[d], 1);
    }
}

__global__ void dinv_kernel(const float* __restrict__ deg, float* dinv, int n) {
    int i = blockIdx.x * blockDim.x + threadIdx.x;
    if (i < n) dinv[i] = rsqrtf(deg[i]);
}

__global__ void norm_kernel(const int* __restrict__ src,
                            const int* __restrict__ dst,
                            const float* __restrict__ w,
                            const float* __restrict__ dinv,
                            float* norm, int e) {
    int i = blockIdx.x * blockDim.x + threadIdx.x;
    if (i < e) norm[i] = dinv[src[i]] * w[i] * dinv[dst[i]];
}

// ---------------- CSR build: 2-level scan + cursor fill ----------------
__global__ void scan_block_kernel(const int* __restrict__ cnt,
                                  int* __restrict__ scan,
                                  int* __restrict__ bsum, int n) {
    __shared__ int sh[SCAN_B];
    int i = blockIdx.x * SCAN_B + threadIdx.x;
    sh[threadIdx.x] = (i < n) ? cnt[i] : 0;
    __syncthreads();
    #pragma unroll
    for (int o = 1; o < SCAN_B; o <<= 1) {
        int t = (threadIdx.x >= o) ? sh[threadIdx.x - o] : 0;
        __syncthreads();
        sh[threadIdx.x] += t;
        __syncthreads();
    }
    if (i < n) scan[i] = sh[threadIdx.x];
    if (threadIdx.x == SCAN_B - 1) bsum[blockIdx.x] = sh[SCAN_B - 1];
}

__global__ void scan_bsum_kernel(int* __restrict__ bsum, int nb) {
    __shared__ int sh[SCAN_B];
    sh[threadIdx.x] = (threadIdx.x < nb) ? bsum[threadIdx.x] : 0;
    __syncthreads();
    #pragma unroll
    for (int o = 1; o < SCAN_B; o <<= 1) {
        int t = (threadIdx.x >= o) ? sh[threadIdx.x - o] : 0;
        __syncthreads();
        sh[threadIdx.x] += t;
        __syncthreads();
    }
    if (threadIdx.x < nb) bsum[threadIdx.x] = sh[threadIdx.x];
}

__global__ void rowptr_kernel(const int* __restrict__ scan,
                              const int* __restrict__ bsum,
                              int* __restrict__ rowptr, int n) {
    int i = blockIdx.x * SCAN_B + threadIdx.x;
    if (i < n) {
        int off = (blockIdx.x > 0) ? bsum[blockIdx.x - 1] : 0;
        rowptr[i + 1] = scan[i] + off;
    }
    if (i == 0) rowptr[0] = 0;
}

__global__ void fill_kernel(const int* __restrict__ src,
                            const int* __restrict__ dst,
                            const float* __restrict__ norm,
                            const int* __restrict__ rowptr,
                            int* __restrict__ cur,
                            int* __restrict__ esrc,
                            float* __restrict__ enorm, int e) {
    int i = blockIdx.x * blockDim.x + threadIdx.x;
    if (i < e) {
        int d = dst[i];
        int p = rowptr[d] + atomicAdd(&cur[d], 1);
        esrc[p]  = src[i];
        enorm[p] = norm[i];
    }
}

// ---------------- tiled SGEMM: C[M,Ncols] = A[M,K] @ B[Ncols,K]^T ----------------
__global__ __launch_bounds__(256)
void sgemm_nt_kernel(const float* __restrict__ A, const float* __restrict__ B,
                     float* __restrict__ C, int M, int Ncols, int K) {
    constexpr int BM = 128, BN = 128, BK = 8, TM = 8, TN = 8;
    __shared__ float As[BK][BM];
    __shared__ float Bs[BK][BN];

    int tid = threadIdx.x;
    int tx = tid % 16;
    int ty = tid / 16;
    int block_row = blockIdx.y * BM;
    int block_col = blockIdx.x * BN;

    int ld_row  = tid >> 1;
    int ld_col4 = (tid & 1) * 4;

    float acc[TM][TN];
    #pragma unroll
    for (int i = 0; i < TM; i++)
        #pragma unroll
        for (int j = 0; j < TN; j++) acc[i][j] = 0.0f;

    for (int k0 = 0; k0 < K; k0 += BK) {
        float4 av = make_float4(0.f, 0.f, 0.f, 0.f);
        int gr = block_row + ld_row;
        if (gr < M)
            av = *reinterpret_cast<const float4*>(A + (size_t)gr * K + k0 + ld_col4);
        As[ld_col4 + 0][ld_row] = av.x;
        As[ld_col4 + 1][ld_row] = av.y;
        As[ld_col4 + 2][ld_row] = av.z;
        As[ld_col4 + 3][ld_row] = av.w;

        int gn = block_col + ld_row;
        float4 bv = *reinterpret_cast<const float4*>(B + (size_t)gn * K + k0 + ld_col4);
        Bs[ld_col4 + 0][ld_row] = bv.x;
        Bs[ld_col4 + 1][ld_row] = bv.y;
        Bs[ld_col4 + 2][ld_row] = bv.z;
        Bs[ld_col4 + 3][ld_row] = bv.w;

        __syncthreads();

        #pragma unroll
        for (int kk = 0; kk < BK; kk++) {
            float ar[TM], br[TN];
            #pragma unroll
            for (int i = 0; i < TM; i++) ar[i] = As[kk][ty * TM + i];
            #pragma unroll
            for (int j = 0; j < TN; j++) br[j] = Bs[kk][tx * TN + j];
            #pragma unroll
            for (int i = 0; i < TM; i++)
                #pragma unroll
                for (int j = 0; j < TN; j++)
                    acc[i][j] += ar[i] * br[j];
        }
        __syncthreads();
    }

    #pragma unroll
    for (int i = 0; i < TM; i++) {
        int gr = block_row + ty * TM + i;
        if (gr < M) {
            float4 c0 = make_float4(acc[i][0], acc[i][1], acc[i][2], acc[i][3]);
            float4 c1 = make_float4(acc[i][4], acc[i][5], acc[i][6], acc[i][7]);
            float* cp = C + (size_t)gr * Ncols + block_col + tx * TN;
            *reinterpret_cast<float4*>(cp)     = c0;
            *reinterpret_cast<float4*>(cp + 4) = c1;
        }
    }
}

// ---------------- layer-1 gather: out = relu(sum norm*h[src] + dinv^2*h[i] + b1) ----
// D = 256: warp per node, lane covers float4 indices {lane, lane+32}.
__global__ __launch_bounds__(256)
void gather1_kernel(const float* __restrict__ h,
                    const int* __restrict__ rowptr,
                    const int* __restrict__ esrc,
                    const float* __restrict__ enorm,
                    const float* __restrict__ dinv,
                    const float* __restrict__ bias,
                    float* __restrict__ out, int n) {
    int node = blockIdx.x * (blockDim.x >> 5) + (threadIdx.x >> 5);
    int lane = threadIdx.x & 31;
    if (node >= n) return;

    const float4* hp = reinterpret_cast<const float4*>(h);
    float s = dinv[node]; s *= s;

    float4 a0 = hp[(size_t)node * 64 + lane];
    float4 a1 = hp[(size_t)node * 64 + 32 + lane];
    float4 b0 = reinterpret_cast<const float4*>(bias)[lane];
    float4 b1v = reinterpret_cast<const float4*>(bias)[lane + 32];
    a0.x = a0.x * s + b0.x;  a0.y = a0.y * s + b0.y;
    a0.z = a0.z * s + b0.z;  a0.w = a0.w * s + b0.w;
    a1.x = a1.x * s + b1v.x; a1.y = a1.y * s + b1v.y;
    a1.z = a1.z * s + b1v.z; a1.w = a1.w * s + b1v.w;

    int beg = rowptr[node], end = rowptr[node + 1];
    for (int e = beg; e < end; e++) {
        int   si = esrc[e];
        float w  = enorm[e];
        float4 v0 = hp[(size_t)si * 64 + lane];
        float4 v1 = hp[(size_t)si * 64 + 32 + lane];
        a0.x += w * v0.x; a0.y += w * v0.y; a0.z += w * v0.z; a0.w += w * v0.w;
        a1.x += w * v1.x; a1.y += w * v1.y; a1.z += w * v1.z; a1.w += w * v1.w;
    }

    // fused ReLU
    a0.x = fmaxf(a0.x, 0.f); a0.y = fmaxf(a0.y, 0.f);
    a0.z = fmaxf(a0.z, 0.f); a0.w = fmaxf(a0.w, 0.f);
    a1.x = fmaxf(a1.x, 0.f); a1.y = fmaxf(a1.y, 0.f);
    a1.z = fmaxf(a1.z, 0.f); a1.w = fmaxf(a1.w, 0.f);

    float4* op = reinterpret_cast<float4*>(out) + (size_t)node * 64;
    op[lane]      = a0;
    op[lane + 32] = a1;
}

// ---------------- layer-2 gather + fused LayerNorm ----------------
// D = 128: warp per node, lane covers float4 index lane. Final row stays in
// registers; LayerNorm computed in-warp and written straight to d_out.
__global__ __launch_bounds__(256)
void gather2_ln_kernel(const float* __restrict__ h,
                       const int* __restrict__ rowptr,
                       const int* __restrict__ esrc,
                       const float* __restrict__ enorm,
                       const float* __restrict__ dinv,
                       const float* __restrict__ bias,
                       const float* __restrict__ gamma,
                       const float* __restrict__ beta,
                       float* __restrict__ out, int n) {
    int node = blockIdx.x * (blockDim.x >> 5) + (threadIdx.x >> 5);
    int lane = threadIdx.x & 31;
    if (node >= n) return;

    const float4* hp = reinterpret_cast<const float4*>(h);
    float s = dinv[node]; s *= s;

    float4 a = hp[(size_t)node * 32 + lane];
    float4 bv = reinterpret_cast<const float4*>(bias)[lane];
    a.x = a.x * s + bv.x; a.y = a.y * s + bv.y;
    a.z = a.z * s + bv.z; a.w = a.w * s + bv.w;

    int beg = rowptr[node], end = rowptr[node + 1];
    for (int e = beg; e < end; e++) {
        int   si = esrc[e];
        float w  = enorm[e];
        float4 v = hp[(size_t)si * 32 + lane];
        a.x += w * v.x; a.y += w * v.y; a.z += w * v.z; a.w += w * v.w;
    }

    // in-warp LayerNorm over 128 values
    float sum = a.x + a.y + a.z + a.w;
    #pragma unroll
    for (int o = 16; o; o >>= 1) sum += __shfl_xor_sync(0xFFFFFFFFu, sum, o);
    float mu = sum * (1.0f / 128.0f);
    float dx = a.x - mu, dy = a.y - mu, dz = a.z - mu, dw = a.w - mu;
    float sq = dx * dx + dy * dy + dz * dz + dw * dw;
    #pragma unroll
    for (int o = 16; o; o >>= 1) sq += __shfl_xor_sync(0xFFFFFFFFu, sq, o);
    float inv = rsqrtf(sq * (1.0f / 128.0f) + 1e-5f);

    float4 g = reinterpret_cast<const float4*>(gamma)[lane];
    float4 b = reinterpret_cast<const float4*>(beta)[lane];
    float4 o4;
    o4.x = dx * inv * g.x + b.x;
    o4.y = dy * inv * g.y + b.y;
    o4.z = dz * inv * g.z + b.z;
    o4.w = dw * inv * g.w + b.w;
    reinterpret_cast<float4*>(out)[(size_t)node * 32 + lane] = o4;
}

// ---------------- host launcher ----------------
extern "C" void kernel_launch(void* const* d_in, const int* in_sizes, int n_in,
                              void* d_out, int out_size) {
    const float* x     = (const float*)d_in[0];
    const int*   ei    = (const int*)d_in[1];   // int32 (JAX x64 disabled)
    const float* w     = (const float*)d_in[2];
    const float* W1    = (const float*)d_in[3];
    const float* b1    = (const float*)d_in[4];
    const float* W2    = (const float*)d_in[5];
    const float* b2    = (const float*)d_in[6];
    const float* gamma = (const float*)d_in[7];
    const float* beta  = (const float*)d_in[8];
    float*       out   = (float*)d_out;

    const int* src = ei;
    const int* dst = ei + EE;

    float *deg, *dinv, *nrm, *h1, *out1, *h2, *enorm;
    int *cnt, *cur, *scan, *bsum, *rowptr, *esrc;
    cudaGetSymbolAddress((void**)&deg,    g_deg);
    cudaGetSymbolAddress((void**)&dinv,   g_dinv);
    cudaGetSymbolAddress((void**)&nrm,    g_norm);
    cudaGetSymbolAddress((void**)&cnt,    g_cnt);
    cudaGetSymbolAddress((void**)&cur,    g_cur);
    cudaGetSymbolAddress((void**)&scan,   g_scan);
    cudaGetSymbolAddress((void**)&bsum,   g_bsum);
    cudaGetSymbolAddress((void**)&rowptr, g_rowptr);
    cudaGetSymbolAddress((void**)&esrc,   g_esrc);
    cudaGetSymbolAddress((void**)&enorm,  g_enorm);
    cudaGetSymbolAddress((void**)&h1,     g_h1);
    cudaGetSymbolAddress((void**)&out1,   g_out1);
    cudaGetSymbolAddress((void**)&h2,     g_h2);

    const int T = 256;

    // normalization coefficients + histogram
    deg_init_kernel<<<(NN + T - 1) / T, T>>>(deg, cnt, cur, NN);
    deg_acc_kernel<<<(EE + T - 1) / T, T>>>(dst, w, deg, cnt, EE);
    dinv_kernel<<<(NN + T - 1) / T, T>>>(deg, dinv, NN);
    norm_kernel<<<(EE + T - 1) / T, T>>>(src, dst, w, dinv, nrm, EE);

    // CSR build (sorted by dst)
    scan_block_kernel<<<NBLK, SCAN_B>>>(cnt, scan, bsum, NN);
    scan_bsum_kernel<<<1, SCAN_B>>>(bsum, NBLK);
    rowptr_kernel<<<NBLK, SCAN_B>>>(scan, bsum, rowptr, NN);
    fill_kernel<<<(EE + T - 1) / T, T>>>(src, dst, nrm, rowptr, cur, esrc, enorm, EE);

    // layer 1: h1 = x @ W1^T; out1 = relu(aggregate + b1)
    {
        dim3 grid(DHID / 128, (NN + 127) / 128);
        sgemm_nt_kernel<<<grid, 256>>>(x, W1, h1, NN, DHID, DIN);
    }
    gather1_kernel<<<(NN + 7) / 8, 256>>>(h1, rowptr, esrc, enorm, dinv, b1, out1, NN);

    // layer 2: h2 = out1 @ W2^T; out = LN(aggregate + b2)
    {
        dim3 grid(DIN / 128, (NN + 127) / 128);
        sgemm_nt_kernel<<<grid, 256>>>(out1, W2, h2, NN, DIN, DHID);
    }
    gather2_ln_kernel<<<(NN + 7) / 8, 256>>>(h2, rowptr, esrc, enorm, dinv, b2, gamma, beta, out, NN);
}

// round 7
// speedup vs baseline: 1.5501x; 1.1102x over previous
#include <cuda_runtime.h>
#include <cuda_bf16.h>
#include <cstdint>

// Problem constants (fixed by the reference)
constexpr int NN   = 50000;
constexpr int EE   = 800000;
constexpr int DIN  = 128;
constexpr int DHID = 256;
constexpr int SCAN_B = 256;
constexpr int NBLK   = (NN + SCAN_B - 1) / SCAN_B;   // 196

// ---------------- scratch (device globals: allocation-free) ----------------
__device__ __align__(16) float g_deg  [NN];
__device__ __align__(16) float g_dinv [NN];
__device__ __align__(16) float g_norm [EE];
__device__ __align__(16) int   g_cnt  [NN];
__device__ __align__(16) int   g_cur  [NN];
__device__ __align__(16) int   g_scan [NN];
__device__ __align__(16) int   g_bsum [SCAN_B];
__device__ __align__(16) int   g_rowptr[NN + 1];
__device__ __align__(16) int   g_esrc [EE];
__device__ __align__(16) float g_enorm[EE];
__device__ __align__(16) float g_aggx [(size_t)NN * DIN];    // S @ x
__device__ __align__(16) float g_out1 [(size_t)NN * DHID];   // relu(aggx @ W1^T + b1)
__device__ __align__(16) float g_h2   [(size_t)NN * DIN];    // out1 @ W2^T

// ---------------- normalization coefficient kernels ----------------
__global__ void deg_init_kernel(float* deg, int* cnt, int* cur, int n) {
    int i = blockIdx.x * blockDim.x + threadIdx.x;
    if (i < n) { deg[i] = 1.0f; cnt[i] = 0; cur[i] = 0; }
}

__global__ void deg_acc_kernel(const int* __restrict__ dst,
                               const float* __restrict__ w,
                               float* deg, int* cnt, int e) {
    int i = blockIdx.x * blockDim.x + threadIdx.x;
    if (i < e) {
        int d = dst[i];
        atomicAdd(&deg[d], w[i]);
        atomicAdd(&cnt[d], 1);
    }
}

__global__ void dinv_kernel(const float* __restrict__ deg, float* dinv, int n) {
    int i = blockIdx.x * blockDim.x + threadIdx.x;
    if (i < n) dinv[i] = rsqrtf(deg[i]);
}

__global__ void norm_kernel(const int* __restrict__ src,
                            const int* __restrict__ dst,
                            const float* __restrict__ w,
                            const float* __restrict__ dinv,
                            float* norm, int e) {
    int i = blockIdx.x * blockDim.x + threadIdx.x;
    if (i < e) norm[i] = dinv[src[i]] * w[i] * dinv[dst[i]];
}

// ---------------- CSR build: 2-level scan + cursor fill ----------------
__global__ void scan_block_kernel(const int* __restrict__ cnt,
                                  int* __restrict__ scan,
                                  int* __restrict__ bsum, int n) {
    __shared__ int sh[SCAN_B];
    int i = blockIdx.x * SCAN_B + threadIdx.x;
    sh[threadIdx.x] = (i < n) ? cnt[i] : 0;
    __syncthreads();
    #pragma unroll
    for (int o = 1; o < SCAN_B; o <<= 1) {
        int t = (threadIdx.x >= o) ? sh[threadIdx.x - o] : 0;
        __syncthreads();
        sh[threadIdx.x] += t;
        __syncthreads();
    }
    if (i < n) scan[i] = sh[threadIdx.x];
    if (threadIdx.x == SCAN_B - 1) bsum[blockIdx.x] = sh[SCAN_B - 1];
}

__global__ void scan_bsum_kernel(int* __restrict__ bsum, int nb) {
    __shared__ int sh[SCAN_B];
    sh[threadIdx.x] = (threadIdx.x < nb) ? bsum[threadIdx.x] : 0;
    __syncthreads();
    #pragma unroll
    for (int o = 1; o < SCAN_B; o <<= 1) {
        int t = (threadIdx.x >= o) ? sh[threadIdx.x - o] : 0;
        __syncthreads();
        sh[threadIdx.x] += t;
        __syncthreads();
    }
    if (threadIdx.x < nb) bsum[threadIdx.x] = sh[threadIdx.x];
}

__global__ void rowptr_kernel(const int* __restrict__ scan,
                              const int* __restrict__ bsum,
                              int* __restrict__ rowptr, int n) {
    int i = blockIdx.x * SCAN_B + threadIdx.x;
    if (i < n) {
        int off = (blockIdx.x > 0) ? bsum[blockIdx.x - 1] : 0;
        rowptr[i + 1] = scan[i] + off;
    }
    if (i == 0) rowptr[0] = 0;
}

__global__ void fill_kernel(const int* __restrict__ src,
                            const int* __restrict__ dst,
                            const float* __restrict__ norm,
                            const int* __restrict__ rowptr,
                            int* __restrict__ cur,
                            int* __restrict__ esrc,
                            float* __restrict__ enorm, int e) {
    int i = blockIdx.x * blockDim.x + threadIdx.x;
    if (i < e) {
        int d = dst[i];
        int p = rowptr[d] + atomicAdd(&cur[d], 1);
        esrc[p]  = src[i];
        enorm[p] = norm[i];
    }
}

// ---------------- D=128 gather (no epilogue): aggx = dinv^2*x_i + sum norm*x[src] ----
__global__ __launch_bounds__(256)
void gather0_kernel(const float* __restrict__ x,
                    const int* __restrict__ rowptr,
                    const int* __restrict__ esrc,
                    const float* __restrict__ enorm,
                    const float* __restrict__ dinv,
                    float* __restrict__ out, int n) {
    int node = blockIdx.x * (blockDim.x >> 5) + (threadIdx.x >> 5);
    int lane = threadIdx.x & 31;
    if (node >= n) return;

    const float4* xp = reinterpret_cast<const float4*>(x);
    float s = dinv[node]; s *= s;

    float4 a = xp[(size_t)node * 32 + lane];
    a.x *= s; a.y *= s; a.z *= s; a.w *= s;

    int beg = rowptr[node], end = rowptr[node + 1];
    for (int e = beg; e < end; e++) {
        int   si = esrc[e];
        float w  = enorm[e];
        float4 v = xp[(size_t)si * 32 + lane];
        a.x += w * v.x; a.y += w * v.y; a.z += w * v.z; a.w += w * v.w;
    }
    reinterpret_cast<float4*>(out)[(size_t)node * 32 + lane] = a;
}

// ---------------- double-buffered SGEMM: C = A[M,K] @ B[Ncols,K]^T (+bias, relu) ----
// BM=BN=128, BK=16, 256 threads, 8x8 microtile, 2-stage smem pipeline.
template<bool BIAS_RELU>
__global__ __launch_bounds__(256)
void sgemm_nt_db_kernel(const float* __restrict__ A, const float* __restrict__ B,
                        const float* __restrict__ bias,
                        float* __restrict__ C, int M, int Ncols, int K) {
    constexpr int BM = 128, BN = 128, BK = 16, TM = 8, TN = 8;
    __shared__ float As[2][BK][BM];
    __shared__ float Bs[2][BK][BN];

    int tid = threadIdx.x;
    int tx = tid % 16;
    int ty = tid / 16;
    int block_row = blockIdx.y * BM;
    int block_col = blockIdx.x * BN;

    // Each thread loads 2 float4 per tile: row ld_row, cols [c0, c0+4)/[c0+4, c0+8)
    int ld_row = tid >> 1;          // 0..127
    int c0     = (tid & 1) * 8;     // 0 or 8

    int a_row = block_row + ld_row;
    bool a_ok = a_row < M;
    const float* a_base = A + (size_t)(a_ok ? a_row : 0) * K + c0;
    const float* b_base = B + (size_t)(block_col + ld_row) * K + c0;

    float acc[TM][TN];
    #pragma unroll
    for (int i = 0; i < TM; i++)
        #pragma unroll
        for (int j = 0; j < TN; j++) acc[i][j] = 0.0f;

    // prologue: load tile 0 into buffer 0
    {
        float4 av0 = make_float4(0.f,0.f,0.f,0.f), av1 = make_float4(0.f,0.f,0.f,0.f);
        if (a_ok) {
            av0 = *reinterpret_cast<const float4*>(a_base);
            av1 = *reinterpret_cast<const float4*>(a_base + 4);
        }
        float4 bv0 = *reinterpret_cast<const float4*>(b_base);
        float4 bv1 = *reinterpret_cast<const float4*>(b_base + 4);
        As[0][c0+0][ld_row]=av0.x; As[0][c0+1][ld_row]=av0.y;
        As[0][c0+2][ld_row]=av0.z; As[0][c0+3][ld_row]=av0.w;
        As[0][c0+4][ld_row]=av1.x; As[0][c0+5][ld_row]=av1.y;
        As[0][c0+6][ld_row]=av1.z; As[0][c0+7][ld_row]=av1.w;
        Bs[0][c0+0][ld_row]=bv0.x; Bs[0][c0+1][ld_row]=bv0.y;
        Bs[0][c0+2][ld_row]=bv0.z; Bs[0][c0+3][ld_row]=bv0.w;
        Bs[0][c0+4][ld_row]=bv1.x; Bs[0][c0+5][ld_row]=bv1.y;
        Bs[0][c0+6][ld_row]=bv1.z; Bs[0][c0+7][ld_row]=bv1.w;
    }
    __syncthreads();

    int cur = 0;
    for (int k0 = BK; k0 <= K; k0 += BK) {
        float4 av0, av1, bv0, bv1;
        bool has_next = k0 < K;
        if (has_next) {
            av0 = make_float4(0.f,0.f,0.f,0.f); av1 = av0;
            if (a_ok) {
                av0 = *reinterpret_cast<const float4*>(a_base + k0);
                av1 = *reinterpret_cast<const float4*>(a_base + k0 + 4);
            }
            bv0 = *reinterpret_cast<const float4*>(b_base + k0);
            bv1 = *reinterpret_cast<const float4*>(b_base + k0 + 4);
        }

        #pragma unroll
        for (int kk = 0; kk < BK; kk++) {
            float ar[TM], br[TN];
            #pragma unroll
            for (int i = 0; i < TM; i++) ar[i] = As[cur][kk][ty * TM + i];
            #pragma unroll
            for (int j = 0; j < TN; j++) br[j] = Bs[cur][kk][tx * TN + j];
            #pragma unroll
            for (int i = 0; i < TM; i++)
                #pragma unroll
                for (int j = 0; j < TN; j++)
                    acc[i][j] += ar[i] * br[j];
        }

        if (has_next) {
            int nxt = cur ^ 1;
            As[nxt][c0+0][ld_row]=av0.x; As[nxt][c0+1][ld_row]=av0.y;
            As[nxt][c0+2][ld_row]=av0.z; As[nxt][c0+3][ld_row]=av0.w;
            As[nxt][c0+4][ld_row]=av1.x; As[nxt][c0+5][ld_row]=av1.y;
            As[nxt][c0+6][ld_row]=av1.z; As[nxt][c0+7][ld_row]=av1.w;
            Bs[nxt][c0+0][ld_row]=bv0.x; Bs[nxt][c0+1][ld_row]=bv0.y;
            Bs[nxt][c0+2][ld_row]=bv0.z; Bs[nxt][c0+3][ld_row]=bv0.w;
            Bs[nxt][c0+4][ld_row]=bv1.x; Bs[nxt][c0+5][ld_row]=bv1.y;
            Bs[nxt][c0+6][ld_row]=bv1.z; Bs[nxt][c0+7][ld_row]=bv1.w;
            __syncthreads();
            cur = nxt;
        }
    }

    // epilogue
    float4 bias0 = make_float4(0.f,0.f,0.f,0.f), bias1 = bias0;
    if (BIAS_RELU) {
        const float* bp = bias + block_col + tx * TN;
        bias0 = *reinterpret_cast<const float4*>(bp);
        bias1 = *reinterpret_cast<const float4*>(bp + 4);
    }
    #pragma unroll
    for (int i = 0; i < TM; i++) {
        int gr = block_row + ty * TM + i;
        if (gr < M) {
            float4 c0v = make_float4(acc[i][0], acc[i][1], acc[i][2], acc[i][3]);
            float4 c1v = make_float4(acc[i][4], acc[i][5], acc[i][6], acc[i][7]);
            if (BIAS_RELU) {
                c0v.x = fmaxf(c0v.x + bias0.x, 0.f); c0v.y = fmaxf(c0v.y + bias0.y, 0.f);
                c0v.z = fmaxf(c0v.z + bias0.z, 0.f); c0v.w = fmaxf(c0v.w + bias0.w, 0.f);
                c1v.x = fmaxf(c1v.x + bias1.x, 0.f); c1v.y = fmaxf(c1v.y + bias1.y, 0.f);
                c1v.z = fmaxf(c1v.z + bias1.z, 0.f); c1v.w = fmaxf(c1v.w + bias1.w, 0.f);
            }
            float* cp = C + (size_t)gr * Ncols + block_col + tx * TN;
            *reinterpret_cast<float4*>(cp)     = c0v;
            *reinterpret_cast<float4*>(cp + 4) = c1v;
        }
    }
}

// ---------------- layer-2 gather + fused LayerNorm ----------------
__global__ __launch_bounds__(256)
void gather2_ln_kernel(const float* __restrict__ h,
                       const int* __restrict__ rowptr,
                       const int* __restrict__ esrc,
                       const float* __restrict__ enorm,
                       const float* __restrict__ dinv,
                       const float* __restrict__ bias,
                       const float* __restrict__ gamma,
                       const float* __restrict__ beta,
                       float* __restrict__ out, int n) {
    int node = blockIdx.x * (blockDim.x >> 5) + (threadIdx.x >> 5);
    int lane = threadIdx.x & 31;
    if (node >= n) return;

    const float4* hp = reinterpret_cast<const float4*>(h);
    float s = dinv[node]; s *= s;

    float4 a = hp[(size_t)node * 32 + lane];
    float4 bv = reinterpret_cast<const float4*>(bias)[lane];
    a.x = a.x * s + bv.x; a.y = a.y * s + bv.y;
    a.z = a.z * s + bv.z; a.w = a.w * s + bv.w;

    int beg = rowptr[node], end = rowptr[node + 1];
    for (int e = beg; e < end; e++) {
        int   si = esrc[e];
        float w  = enorm[e];
        float4 v = hp[(size_t)si * 32 + lane];
        a.x += w * v.x; a.y += w * v.y; a.z += w * v.z; a.w += w * v.w;
    }

    float sum = a.x + a.y + a.z + a.w;
    #pragma unroll
    for (int o = 16; o; o >>= 1) sum += __shfl_xor_sync(0xFFFFFFFFu, sum, o);
    float mu = sum * (1.0f / 128.0f);
    float dx = a.x - mu, dy = a.y - mu, dz = a.z - mu, dw = a.w - mu;
    float sq = dx * dx + dy * dy + dz * dz + dw * dw;
    #pragma unroll
    for (int o = 16; o; o >>= 1) sq += __shfl_xor_sync(0xFFFFFFFFu, sq, o);
    float inv = rsqrtf(sq * (1.0f / 128.0f) + 1e-5f);

    float4 g = reinterpret_cast<const float4*>(gamma)[lane];
    float4 b = reinterpret_cast<const float4*>(beta)[lane];
    float4 o4;
    o4.x = dx * inv * g.x + b.x;
    o4.y = dy * inv * g.y + b.y;
    o4.z = dz * inv * g.z + b.z;
    o4.w = dw * inv * g.w + b.w;
    reinterpret_cast<float4*>(out)[(size_t)node * 32 + lane] = o4;
}

// ---------------- host launcher ----------------
extern "C" void kernel_launch(void* const* d_in, const int* in_sizes, int n_in,
                              void* d_out, int out_size) {
    const float* x     = (const float*)d_in[0];
    const int*   ei    = (const int*)d_in[1];   // int32 (JAX x64 disabled)
    const float* w     = (const float*)d_in[2];
    const float* W1    = (const float*)d_in[3];
    const float* b1    = (const float*)d_in[4];
    const float* W2    = (const float*)d_in[5];
    const float* b2    = (const float*)d_in[6];
    const float* gamma = (const float*)d_in[7];
    const float* beta  = (const float*)d_in[8];
    float*       out   = (float*)d_out;

    const int* src = ei;
    const int* dst = ei + EE;

    float *deg, *dinv, *nrm, *aggx, *out1, *h2, *enorm;
    int *cnt, *cur, *scan, *bsum, *rowptr, *esrc;
    cudaGetSymbolAddress((void**)&deg,    g_deg);
    cudaGetSymbolAddress((void**)&dinv,   g_dinv);
    cudaGetSymbolAddress((void**)&nrm,    g_norm);
    cudaGetSymbolAddress((void**)&cnt,    g_cnt);
    cudaGetSymbolAddress((void**)&cur,    g_cur);
    cudaGetSymbolAddress((void**)&scan,   g_scan);
    cudaGetSymbolAddress((void**)&bsum,   g_bsum);
    cudaGetSymbolAddress((void**)&rowptr, g_rowptr);
    cudaGetSymbolAddress((void**)&esrc,   g_esrc);
    cudaGetSymbolAddress((void**)&enorm,  g_enorm);
    cudaGetSymbolAddress((void**)&aggx,   g_aggx);
    cudaGetSymbolAddress((void**)&out1,   g_out1);
    cudaGetSymbolAddress((void**)&h2,     g_h2);

    const int T = 256;

    // normalization coefficients + histogram
    deg_init_kernel<<<(NN + T - 1) / T, T>>>(deg, cnt, cur, NN);
    deg_acc_kernel<<<(EE + T - 1) / T, T>>>(dst, w, deg, cnt, EE);
    dinv_kernel<<<(NN + T - 1) / T, T>>>(deg, dinv, NN);
    norm_kernel<<<(EE + T - 1) / T, T>>>(src, dst, w, dinv, nrm, EE);

    // CSR build (sorted by dst)
    scan_block_kernel<<<NBLK, SCAN_B>>>(cnt, scan, bsum, NN);
    scan_bsum_kernel<<<1, SCAN_B>>>(bsum, NBLK);
    rowptr_kernel<<<NBLK, SCAN_B>>>(scan, bsum, rowptr, NN);
    fill_kernel<<<(EE + T - 1) / T, T>>>(src, dst, nrm, rowptr, cur, esrc, enorm, EE);

    // layer 1 (reordered): aggx = S @ x ; out1 = relu(aggx @ W1^T + b1)
    gather0_kernel<<<(NN + 7) / 8, 256>>>(x, rowptr, esrc, enorm, dinv, aggx, NN);
    {
        dim3 grid(DHID / 128, (NN + 127) / 128);
        sgemm_nt_db_kernel<true><<<grid, 256>>>(aggx, W1, b1, out1, NN, DHID, DIN);
    }

    // layer 2: h2 = out1 @ W2^T ; out = LN(S @ h2 + b2)
    {
        dim3 grid(DIN / 128, (NN + 127) / 128);
        sgemm_nt_db_kernel<false><<<grid, 256>>>(out1, W2, nullptr, h2, NN, DIN, DHID);
    }
    gather2_ln_kernel<<<(NN + 7) / 8, 256>>>(h2, rowptr, esrc, enorm, dinv, b2, gamma, beta, out, NN);
}